// round 3
// baseline (speedup 1.0000x reference)
#include <cuda_runtime.h>

#define LLEN 1024
#define NB   64
#define TILE 128

// ---- device scratch (no allocations allowed) ----
__device__ float g_cat [NB * 192 * LLEN];
__device__ float g_dec [NB * 192 * LLEN];
__device__ float g_encU[NB * 64  * LLEN];
__device__ int   g_ids [NB];

// ------------------------------------------------------------------
__global__ void ids_kernel(const float* __restrict__ x) {
    int b = threadIdx.x;
    if (b < NB) g_ids[b] = (int)x[(long)b * (LLEN + 1) + LLEN];
}

// ------------------------------------------------------------------
// Fused block: y = relu(W2 @ relu(dilated_conv5(x, W1) + b1) + b2)
// conv1: CIN -> 128 (k=5, dilation DIL), conv2: 128 -> 32 (1x1)
// Computed in two co-halves of 64 so hs is 64 x TILE (smem ~93KB -> 2 CTA/SM).
// Grid (L/TILE, B), 512 threads.
// smem: xs[CIN][XW] | ws1[CCH][5][64] | hs[64][TILE] | ws2[128][32] | b1s | b2s
// ------------------------------------------------------------------
template<int CIN, int DIL>
__global__ void __launch_bounds__(512, 2)
block_kernel(const float* __restrict__ xin, long in_samp_stride, int in_ch_stride,
             const float* __restrict__ w1, const float* __restrict__ b1,
             const float* __restrict__ w2, const float* __restrict__ b2,
             float* __restrict__ yout, long out_samp_stride,
             const int* __restrict__ ids,
             long w1_cs, long b1_cs, long w2_cs, long b2_cs)
{
    constexpr int XW  = TILE + 4 * DIL;          // input tile incl. halo
    constexpr int CCH = (CIN < 8) ? CIN : 8;     // weight chunk (input channels)
    extern __shared__ float sm[];
    float* xs  = sm;                             // CIN * XW
    float* ws1 = xs  + CIN * XW;                 // CCH * 5 * 64   [cil][t][co]
    float* hs  = ws1 + CCH * 320;                // 64 * TILE
    float* ws2 = hs  + 64 * TILE;                // 128 * 32       [k][co2]
    float* b1s = ws2 + 128 * 32;                 // 128
    float* b2s = b1s + 128;                      // 32

    const int b    = blockIdx.y;
    const int l0   = blockIdx.x * TILE;
    const int tid  = threadIdx.x;
    const int warp = tid >> 5;
    const int ln   = tid & 31;

    const float* w1p = w1;
    const float* b1p = b1;
    const float* w2p = w2;
    const float* b2p = b2;
    if (ids) {
        int c = ids[b];
        w1p += (long)c * w1_cs;  b1p += (long)c * b1_cs;
        w2p += (long)c * w2_cs;  b2p += (long)c * b2_cs;
    }

    // ---- stage input tile (halo 2*DIL each side, zero-padded) ----
    const float* xb = xin + (long)b * in_samp_stride;
    for (int i = tid; i < CIN * XW; i += 512) {
        int ci = i / XW, j = i - ci * XW;
        int pos = l0 - 2 * DIL + j;
        xs[i] = (pos >= 0 && pos < LLEN) ? xb[(long)ci * in_ch_stride + pos] : 0.f;
    }
    if (tid < 128) b1s[tid] = b1p[tid];
    if (tid < 32)  b2s[tid] = b2p[tid];
    // ws2: [k][co2]; consecutive tid -> consecutive smem (conflict-free store)
    for (int i = tid; i < 32 * 128; i += 512) {
        int co = i & 31, k = i >> 5;
        ws2[k * 32 + co] = w2p[co * 128 + k];
    }

    // conv2 accumulators persist across both halves: warp owns co2 = 2*warp..+2
    float a2[2][4];
    #pragma unroll
    for (int c = 0; c < 2; c++)
        #pragma unroll
        for (int i = 0; i < 4; i++) a2[c][i] = 0.f;

    #pragma unroll
    for (int half = 0; half < 2; half++) {
        const int coB = half * 64;

        // ---- conv1 for this co-half: warp owns 4 co, lane owns l = ln+32*i ----
        float acc[4][4];
        #pragma unroll
        for (int c = 0; c < 4; c++)
            #pragma unroll
            for (int i = 0; i < 4; i++) acc[c][i] = 0.f;

        for (int ci0 = 0; ci0 < CIN; ci0 += CCH) {
            __syncthreads();   // also orders prev-half conv2 reads vs ws1 restage
            for (int i = tid; i < CCH * 320; i += 512) {
                int cil = i / 320;
                int r   = i - cil * 320;
                int t   = r >> 6;
                int co  = r & 63;
                ws1[i] = w1p[(long)(coB + co) * (CIN * 5) + (ci0 + cil) * 5 + t];
            }
            __syncthreads();
            #pragma unroll
            for (int cil = 0; cil < CCH; cil++) {
                const float* xrow  = xs + (ci0 + cil) * XW + ln;
                const float* wbase = ws1 + cil * 320 + warp * 4;
                #pragma unroll
                for (int t = 0; t < 5; t++) {
                    float4 w4 = *(const float4*)(wbase + t * 64);   // broadcast
                    float xv[4];
                    #pragma unroll
                    for (int i = 0; i < 4; i++) xv[i] = xrow[32 * i + t * DIL];
                    #pragma unroll
                    for (int i = 0; i < 4; i++) {
                        acc[0][i] = fmaf(w4.x, xv[i], acc[0][i]);
                        acc[1][i] = fmaf(w4.y, xv[i], acc[1][i]);
                        acc[2][i] = fmaf(w4.z, xv[i], acc[2][i]);
                        acc[3][i] = fmaf(w4.w, xv[i], acc[3][i]);
                    }
                }
            }
        }
        __syncthreads();
        // ---- bias + relu -> hs (co local to half) ----
        #pragma unroll
        for (int c = 0; c < 4; c++) {
            int co = warp * 4 + c;
            float bb = b1s[coB + co];
            #pragma unroll
            for (int i = 0; i < 4; i++) {
                float v = acc[c][i] + bb;
                hs[co * TILE + ln + 32 * i] = v > 0.f ? v : 0.f;
            }
        }
        __syncthreads();

        // ---- conv2 partial (k over this half) ----
        #pragma unroll 4
        for (int k = 0; k < 64; k++) {
            float2 w2v = *(const float2*)(ws2 + (coB + k) * 32 + warp * 2); // bcast
            #pragma unroll
            for (int i = 0; i < 4; i++) {
                float xv = hs[k * TILE + ln + 32 * i];
                a2[0][i] = fmaf(w2v.x, xv, a2[0][i]);
                a2[1][i] = fmaf(w2v.y, xv, a2[1][i]);
            }
        }
    }

    float* yb = yout + (long)b * out_samp_stride;
    {
        int co2 = warp * 2;
        float bb0 = b2s[co2], bb1 = b2s[co2 + 1];
        #pragma unroll
        for (int i = 0; i < 4; i++) {
            float v0 = a2[0][i] + bb0;
            float v1 = a2[1][i] + bb1;
            yb[(long)co2 * LLEN + l0 + ln + 32 * i]       = v0 > 0.f ? v0 : 0.f;
            yb[(long)(co2 + 1) * LLEN + l0 + ln + 32 * i] = v1 > 0.f ? v1 : 0.f;
        }
    }
}

// ------------------------------------------------------------------
// compress conv (192 -> 64, 1x1) fused with avgpool(2)+repeat(2)
// TILE 64, 512 threads, 2 CTA/SM. smem: xs[192*64] | ws[192][64] | cb
// ------------------------------------------------------------------
#define CTILE 64
__global__ void __launch_bounds__(512, 2)
comp_kernel(const float* __restrict__ cat, const float* __restrict__ cw,
            const float* __restrict__ cb, float* __restrict__ out)
{
    extern __shared__ float sm[];
    float* xs  = sm;                   // 192 * 64
    float* ws  = xs + 192 * CTILE;     // 192 * 64   [k][co]
    float* cbs = ws + 192 * 64;        // 64

    const int b    = blockIdx.y;
    const int l0   = blockIdx.x * CTILE;
    const int tid  = threadIdx.x;
    const int warp = tid >> 5;
    const int ln   = tid & 31;

    const float* catb = cat + (long)b * 192 * LLEN;
    for (int i = tid; i < 192 * CTILE; i += 512) {
        int ch = i / CTILE, j = i - ch * CTILE;
        xs[i] = catb[(long)ch * LLEN + l0 + j];
    }
    for (int i = tid; i < 64 * 192; i += 512) {
        int co = i & 63, k = i >> 6;
        ws[k * 64 + co] = cw[co * 192 + k];
    }
    if (tid < 64) cbs[tid] = cb[tid];
    __syncthreads();

    // warp owns 4 co; lane owns l = ln + 32*i (i<2)
    float acc[4][2];
    #pragma unroll
    for (int c = 0; c < 4; c++)
        #pragma unroll
        for (int i = 0; i < 2; i++) acc[c][i] = 0.f;

    #pragma unroll 4
    for (int k = 0; k < 192; k++) {
        float4 w4 = *(const float4*)(ws + k * 64 + warp * 4);   // broadcast
        #pragma unroll
        for (int i = 0; i < 2; i++) {
            float xv = xs[k * CTILE + ln + 32 * i];
            acc[0][i] = fmaf(w4.x, xv, acc[0][i]);
            acc[1][i] = fmaf(w4.y, xv, acc[1][i]);
            acc[2][i] = fmaf(w4.z, xv, acc[2][i]);
            acc[3][i] = fmaf(w4.w, xv, acc[3][i]);
        }
    }

    float* ob = out + (long)b * 64 * LLEN;
    #pragma unroll
    for (int c = 0; c < 4; c++) {
        int co = warp * 4 + c;
        float bb = cbs[co];
        #pragma unroll
        for (int i = 0; i < 2; i++) {
            float v = acc[c][i] + bb;
            // avgpool(2)+nearest upsample(2): adjacent lanes hold the l pair
            float p = __shfl_xor_sync(0xffffffffu, v, 1);
            ob[(long)co * LLEN + l0 + ln + 32 * i] = 0.5f * (v + p);
        }
    }
}

// ------------------------------------------------------------------
// final per-sample 1x1 conv: 192 -> 1, weights selected by combination id
// ------------------------------------------------------------------
__global__ void __launch_bounds__(256, 1)
final_kernel(const float* __restrict__ dec, const float* __restrict__ cw,
             const float* __restrict__ cbv, float* __restrict__ out)
{
    __shared__ float ws[192];
    const int b   = blockIdx.x;
    const int tid = threadIdx.x;
    const int c   = g_ids[b];
    if (tid < 192) ws[tid] = cw[(long)c * 192 + tid];
    __syncthreads();
    const float bb = cbv[c];
    const float* db = dec + (long)b * 192 * LLEN;
    for (int l = tid; l < LLEN; l += 256) {
        float s = bb;
        #pragma unroll 8
        for (int ch = 0; ch < 192; ch++) s = fmaf(ws[ch], db[(long)ch * LLEN + l], s);
        out[(long)b * LLEN + l] = s;
    }
}

// ------------------------------------------------------------------
static constexpr int smem_block(int cin, int dil) {
    int xw  = TILE + 4 * dil;
    int cch = cin < 8 ? cin : 8;
    return (cin * xw + cch * 320 + 64 * TILE + 128 * 32 + 160) * 4;
}
static constexpr int SMEM_C = (192 * CTILE + 192 * 64 + 64) * 4;

template<int CIN, int DIL>
static void launch_block(const float* xin, long iss, int ics,
                         const float* w1, const float* b1,
                         const float* w2, const float* b2,
                         float* yout, long oss,
                         const int* ids, long w1cs, long b1cs, long w2cs, long b2cs)
{
    static bool attr_done = false;
    if (!attr_done) {
        cudaFuncSetAttribute(block_kernel<CIN, DIL>,
                             cudaFuncAttributeMaxDynamicSharedMemorySize,
                             smem_block(CIN, DIL));
        attr_done = true;
    }
    dim3 grid(LLEN / TILE, NB);
    block_kernel<CIN, DIL><<<grid, 512, smem_block(CIN, DIL)>>>(
        xin, iss, ics, w1, b1, w2, b2, yout, oss, ids, w1cs, b1cs, w2cs, b2cs);
}

extern "C" void kernel_launch(void* const* d_in, const int* in_sizes, int n_in,
                              void* d_out, int out_size)
{
    const float* x        = (const float*)d_in[0];
    const float* enc0_w1  = (const float*)d_in[1];
    const float* enc0_b1  = (const float*)d_in[2];
    const float* enc0_w2  = (const float*)d_in[3];
    const float* enc0_b2  = (const float*)d_in[4];
    const float* enc_w1   = (const float*)d_in[5];
    const float* enc_b1   = (const float*)d_in[6];
    const float* enc_w2   = (const float*)d_in[7];
    const float* enc_b2   = (const float*)d_in[8];
    const float* comp_w   = (const float*)d_in[9];
    const float* comp_b   = (const float*)d_in[10];
    const float* decf0_w1 = (const float*)d_in[11];
    const float* decf0_b1 = (const float*)d_in[12];
    const float* decf0_w2 = (const float*)d_in[13];
    const float* decf0_b2 = (const float*)d_in[14];
    const float* decf_w1  = (const float*)d_in[15];
    const float* decf_b1  = (const float*)d_in[16];
    const float* decf_w2  = (const float*)d_in[17];
    const float* decf_b2  = (const float*)d_in[18];
    const float* decv_w1  = (const float*)d_in[19];
    const float* decv_b1  = (const float*)d_in[20];
    const float* decv_w2  = (const float*)d_in[21];
    const float* decv_b2  = (const float*)d_in[22];
    const float* decv_cw  = (const float*)d_in[23];
    const float* decv_cb  = (const float*)d_in[24];
    float* out = (float*)d_out;

    float *cat, *dec, *encU;
    int* idsp;
    cudaGetSymbolAddress((void**)&cat,  g_cat);
    cudaGetSymbolAddress((void**)&dec,  g_dec);
    cudaGetSymbolAddress((void**)&encU, g_encU);
    cudaGetSymbolAddress((void**)&idsp, g_ids);

    cudaFuncSetAttribute(comp_kernel, cudaFuncAttributeMaxDynamicSharedMemorySize, SMEM_C);

    const long SS = (long)192 * LLEN;

    ids_kernel<<<1, 64>>>(x);

    // ---- encoder ----
    launch_block<1, 1>(x, (long)(LLEN + 1), 0,
                       enc0_w1, enc0_b1, enc0_w2, enc0_b2,
                       cat, SS, nullptr, 0, 0, 0, 0);
    launch_block<32, 2>(cat + 0 * 32 * LLEN, SS, LLEN,
                        enc_w1 + 0 * 20480, enc_b1 + 0 * 128, enc_w2 + 0 * 4096, enc_b2 + 0 * 32,
                        cat + 1 * 32 * LLEN, SS, nullptr, 0, 0, 0, 0);
    launch_block<32, 4>(cat + 1 * 32 * LLEN, SS, LLEN,
                        enc_w1 + 1 * 20480, enc_b1 + 1 * 128, enc_w2 + 1 * 4096, enc_b2 + 1 * 32,
                        cat + 2 * 32 * LLEN, SS, nullptr, 0, 0, 0, 0);
    launch_block<32, 8>(cat + 2 * 32 * LLEN, SS, LLEN,
                        enc_w1 + 2 * 20480, enc_b1 + 2 * 128, enc_w2 + 2 * 4096, enc_b2 + 2 * 32,
                        cat + 3 * 32 * LLEN, SS, nullptr, 0, 0, 0, 0);
    launch_block<32, 16>(cat + 3 * 32 * LLEN, SS, LLEN,
                         enc_w1 + 3 * 20480, enc_b1 + 3 * 128, enc_w2 + 3 * 4096, enc_b2 + 3 * 32,
                         cat + 4 * 32 * LLEN, SS, nullptr, 0, 0, 0, 0);
    launch_block<32, 32>(cat + 4 * 32 * LLEN, SS, LLEN,
                         enc_w1 + 4 * 20480, enc_b1 + 4 * 128, enc_w2 + 4 * 4096, enc_b2 + 4 * 32,
                         cat + 5 * 32 * LLEN, SS, nullptr, 0, 0, 0, 0);

    // ---- compress + pool + upsample ----
    {
        dim3 grid(LLEN / CTILE, NB);
        comp_kernel<<<grid, 512, SMEM_C>>>(cat, comp_w, comp_b, encU);
    }

    // ---- fixed decoder ----
    launch_block<64, 32>(encU, (long)64 * LLEN, LLEN,
                         decf0_w1, decf0_b1, decf0_w2, decf0_b2,
                         dec, SS, nullptr, 0, 0, 0, 0);
    launch_block<32, 16>(dec + 0 * 32 * LLEN, SS, LLEN,
                         decf_w1 + 0 * 20480, decf_b1 + 0 * 128, decf_w2 + 0 * 4096, decf_b2 + 0 * 32,
                         dec + 1 * 32 * LLEN, SS, nullptr, 0, 0, 0, 0);
    launch_block<32, 8>(dec + 1 * 32 * LLEN, SS, LLEN,
                        decf_w1 + 1 * 20480, decf_b1 + 1 * 128, decf_w2 + 1 * 4096, decf_b2 + 1 * 32,
                        dec + 2 * 32 * LLEN, SS, nullptr, 0, 0, 0, 0);
    launch_block<32, 4>(dec + 2 * 32 * LLEN, SS, LLEN,
                        decf_w1 + 2 * 20480, decf_b1 + 2 * 128, decf_w2 + 2 * 4096, decf_b2 + 2 * 32,
                        dec + 3 * 32 * LLEN, SS, nullptr, 0, 0, 0, 0);

    // ---- variable decoder: only the per-sample selected combination ----
    launch_block<32, 2>(dec + 3 * 32 * LLEN, SS, LLEN,
                        decv_w1 + 0 * 20480, decv_b1 + 0 * 128, decv_w2 + 0 * 4096, decv_b2 + 0 * 32,
                        dec + 4 * 32 * LLEN, SS,
                        idsp, 40960, 256, 8192, 64);
    launch_block<32, 1>(dec + 4 * 32 * LLEN, SS, LLEN,
                        decv_w1 + 1 * 20480, decv_b1 + 1 * 128, decv_w2 + 1 * 4096, decv_b2 + 1 * 32,
                        dec + 5 * 32 * LLEN, SS,
                        idsp, 40960, 256, 8192, 64);

    // ---- final 1x1 conv (per-sample weights) ----
    final_kernel<<<NB, 256>>>(dec, decv_cw, decv_cb, out);
}